// round 11
// baseline (speedup 1.0000x reference)
#include <cuda_runtime.h>
#include <cuda_bf16.h>
#include <float.h>
#include <stdint.h>

#define D    256
#define NE   8192
#define TOK  32768
#define BM   128            // tokens per CTA in main kernel
#define BN   64             // codes per chunk
#define NCH  (NE / BN)      // 128 chunks
#define CAP  32
#define THR  1e-3f          // filter slack >> 2x worst-case bf16 dot error
#define STRB 528            // smem row stride bytes (264 bf16): 16B-aligned, conflict-free

// ---------------- device scratch (no allocations allowed) -------------------
__device__ __align__(16) float g_e2[NE];
__device__ __align__(16) float g_z2[TOK];
__device__ int    g_idx[TOK];
__device__ float  g_partial[TOK];
__device__ uint4  g_ebh[NE * 32];      // emb as bf16, row-major [NE][256]

// ---------------- small helpers --------------------------------------------
__device__ __forceinline__ uint32_t smem_u32(const void* p) {
    uint32_t a;
    asm("{ .reg .u64 t; cvta.to.shared.u64 t, %1; cvt.u32.u64 %0, t; }"
        : "=r"(a) : "l"(p));
    return a;
}
__device__ __forceinline__ uint32_t lds32(uint32_t a) {
    uint32_t v; asm volatile("ld.shared.b32 %0, [%1];" : "=r"(v) : "r"(a)); return v;
}
__device__ __forceinline__ void ldm4(uint32_t* r, uint32_t addr) {
    asm volatile("ldmatrix.sync.aligned.m8n8.x4.shared.b16 {%0,%1,%2,%3}, [%4];"
                 : "=r"(r[0]), "=r"(r[1]), "=r"(r[2]), "=r"(r[3]) : "r"(addr));
}
__device__ __forceinline__ void mma16816(float* c, const uint32_t* a, const uint32_t* b) {
    asm volatile(
        "mma.sync.aligned.m16n8k16.row.col.f32.bf16.bf16.f32 "
        "{%0,%1,%2,%3}, {%4,%5,%6,%7}, {%8,%9}, {%0,%1,%2,%3};"
        : "+f"(c[0]), "+f"(c[1]), "+f"(c[2]), "+f"(c[3])
        : "r"(a[0]), "r"(a[1]), "r"(a[2]), "r"(a[3]), "r"(b[0]), "r"(b[1]));
}
#define CP16(dst, src) asm volatile("cp.async.cg.shared.global [%0], [%1], 16;" :: "r"(dst), "l"(src))
#define CP_COMMIT()    asm volatile("cp.async.commit_group;" ::: "memory")
#define CP_WAIT(n)     asm volatile("cp.async.wait_group %0;" :: "n"(n) : "memory")

__device__ __forceinline__ uint32_t fkey(float x) {          // monotone float->uint
    uint32_t u = __float_as_uint(x);
    return (u & 0x80000000u) ? ~u : (u | 0x80000000u);
}
__device__ __forceinline__ float finv(uint32_t k) {
    uint32_t u = (k & 0x80000000u) ? (k & 0x7FFFFFFFu) : ~k;
    return __uint_as_float(u);
}
__device__ __forceinline__ unsigned pk(__nv_bfloat16 a, __nv_bfloat16 b) {
    return ((unsigned)__bfloat16_as_ushort(b) << 16) | __bfloat16_as_ushort(a);
}

// ---------------- exact row sum-of-squares (round-1 ordering, bit-stable) ---
__global__ void rowsq_emb(const float* __restrict__ emb) {
    int row = blockIdx.x * 8 + (threadIdx.x >> 5), lane = threadIdx.x & 31;
    const float4* e = reinterpret_cast<const float4*>(emb + (size_t)row * D);
    float s = 0.f;
#pragma unroll
    for (int c = 0; c < 2; c++) {
        float4 v = e[lane + 32 * c];
        s += v.x * v.x + v.y * v.y + v.z * v.z + v.w * v.w;
    }
#pragma unroll
    for (int o = 16; o; o >>= 1) s += __shfl_down_sync(0xffffffffu, s, o);
    if (lane == 0) g_e2[row] = s;
}
__global__ void rowsq_z(const float* __restrict__ z) {
    int row = blockIdx.x * 8 + (threadIdx.x >> 5), lane = threadIdx.x & 31;
    const float4* e = reinterpret_cast<const float4*>(z + (size_t)row * D);
    float s = 0.f;
#pragma unroll
    for (int c = 0; c < 2; c++) {
        float4 v = e[lane + 32 * c];
        s += v.x * v.x + v.y * v.y + v.z * v.z + v.w * v.w;
    }
#pragma unroll
    for (int o = 16; o; o >>= 1) s += __shfl_down_sync(0xffffffffu, s, o);
    if (lane == 0) g_z2[row] = s;
}

// ---------------- emb -> bf16 ----------------------------------------------
__global__ void conv_emb(const float* __restrict__ emb) {
    int u = blockIdx.x * 256 + threadIdx.x;          // one float4 each, 524288 total
    float4 v = reinterpret_cast<const float4*>(emb)[u];
    uint2 h;
    h.x = pk(__float2bfloat16(v.x), __float2bfloat16(v.y));
    h.y = pk(__float2bfloat16(v.z), __float2bfloat16(v.w));
    reinterpret_cast<uint2*>(g_ebh)[u] = h;
}

// ---------------- main: bf16 MMA filter + exact fp32 rescore ----------------
// smem layout (bytes):
#define SM_AS   0
#define SM_BS   (BM * STRB)                 // 67584
#define SM_E2   (SM_BS + 2 * BN * STRB)     // 135168
#define SM_RMIN (SM_E2 + 512)               // 135680
#define SM_CNT  (SM_RMIN + BM * 4)          // 136192
#define SM_CAND (SM_CNT + BM * 4)           // 136704
#define SM_TOT  (SM_CAND + BM * CAP * 4)    // 153088

__global__ void __launch_bounds__(256, 1)
vq_main(const float* __restrict__ z, const float* __restrict__ emb,
        float* __restrict__ out_idx) {
    extern __shared__ char sm[];
    const int tid  = threadIdx.x;
    const int lane = tid & 31;
    const int wid  = tid >> 5;
    const int wm   = wid >> 2;             // 0..1 : M half (64 rows)
    const int wn   = wid & 3;              // 0..3 : N quarter (16 cols)
    const int g    = lane >> 2;
    const int t    = lane & 3;
    const int m0   = blockIdx.x * BM;

    float*    e2s  = reinterpret_cast<float*>(sm + SM_E2);
    unsigned* rmin = reinterpret_cast<unsigned*>(sm + SM_RMIN);
    int*      cnt  = reinterpret_cast<int*>(sm + SM_CNT);
    int*      cand = reinterpret_cast<int*>(sm + SM_CAND);

    const uint32_t As = smem_u32(sm) + SM_AS;
    const uint32_t Bs = smem_u32(sm) + SM_BS;

    // init row minima / counters
    if (tid < BM) { rmin[tid] = 0xFFFFFFFFu; cnt[tid] = 0; }

    // ---- convert this CTA's 128 z rows to bf16 into As (padded rows) ----
    for (int u = tid; u < BM * 64; u += 256) {          // 8192 float4s
        int r = u >> 6, c4 = u & 63;
        float4 v = reinterpret_cast<const float4*>(z + (size_t)(m0 + r) * D)[c4];
        uint2 h;
        h.x = pk(__float2bfloat16(v.x), __float2bfloat16(v.y));
        h.y = pk(__float2bfloat16(v.z), __float2bfloat16(v.w));
        *reinterpret_cast<uint2*>(sm + SM_AS + r * STRB + c4 * 8) = h;
    }

    // ---- prefetch chunk 0 ----
    {
        const char* src = reinterpret_cast<const char*>(g_ebh);
        for (int u = tid; u < 2048; u += 256) {
            int r = u >> 5, s16 = u & 31;
            CP16(Bs + r * STRB + s16 * 16, src + (size_t)r * 512 + s16 * 16);
        }
        if (tid < 16)
            CP16(smem_u32(sm) + SM_E2 + tid * 16,
                 reinterpret_cast<const char*>(g_e2) + tid * 16);
        CP_COMMIT();
    }

    // per-thread smem addresses for fragments
    const uint32_t aBase = As + (uint32_t)(wm * 64 + (lane & 15)) * STRB + (lane >> 4) * 16;
    const uint32_t bBase = Bs + (uint32_t)(wn * 16 + g) * STRB + t * 4;

    for (int c = 0; c < NCH; c++) {
        const int buf = c & 1;
        if (c + 1 < NCH) {
            const int nb = 1 - buf;
            const char* src = reinterpret_cast<const char*>(g_ebh) + (size_t)(c + 1) * BN * 512;
            for (int u = tid; u < 2048; u += 256) {
                int r = u >> 5, s16 = u & 31;
                CP16(Bs + nb * (BN * STRB) + r * STRB + s16 * 16,
                     src + (size_t)r * 512 + s16 * 16);
            }
            if (tid < 16)
                CP16(smem_u32(sm) + SM_E2 + nb * 256 + tid * 16,
                     reinterpret_cast<const char*>(g_e2) + (size_t)(c + 1) * 256 + tid * 16);
            CP_COMMIT();
            CP_WAIT(1);
        } else {
            CP_WAIT(0);
        }
        __syncthreads();

        float acc[4][2][4];
#pragma unroll
        for (int mt = 0; mt < 4; mt++)
#pragma unroll
            for (int nt = 0; nt < 2; nt++)
#pragma unroll
                for (int q = 0; q < 4; q++) acc[mt][nt][q] = 0.f;

        const uint32_t bB = bBase + buf * (BN * STRB);
#pragma unroll
        for (int kk = 0; kk < 16; kk++) {
            uint32_t a[4][4], b[2][2];
#pragma unroll
            for (int mt = 0; mt < 4; mt++)
                ldm4(a[mt], aBase + mt * (16 * STRB) + kk * 32);
#pragma unroll
            for (int nt = 0; nt < 2; nt++) {
                uint32_t ad = bB + nt * (8 * STRB) + kk * 32;
                b[nt][0] = lds32(ad);
                b[nt][1] = lds32(ad + 16);
            }
#pragma unroll
            for (int mt = 0; mt < 4; mt++)
#pragma unroll
                for (int nt = 0; nt < 2; nt++)
                    mma16816(acc[mt][nt], a[mt], b[nt]);
        }

        // ---- epilogue: fold scores f = e2 - 2*dot, batched row-min, append ----
#pragma unroll
        for (int nt = 0; nt < 2; nt++) {
            float e2a = e2s[buf * 64 + wn * 16 + nt * 8 + 2 * t];
            float e2b = e2s[buf * 64 + wn * 16 + nt * 8 + 2 * t + 1];
#pragma unroll
            for (int mt = 0; mt < 4; mt++) {
                acc[mt][nt][0] = fmaf(-2.f, acc[mt][nt][0], e2a);
                acc[mt][nt][1] = fmaf(-2.f, acc[mt][nt][1], e2b);
                acc[mt][nt][2] = fmaf(-2.f, acc[mt][nt][2], e2a);
                acc[mt][nt][3] = fmaf(-2.f, acc[mt][nt][3], e2b);
            }
        }
#pragma unroll
        for (int mt = 0; mt < 4; mt++) {
            int r = wm * 64 + mt * 16 + g;
            float fa = fminf(fminf(acc[mt][0][0], acc[mt][0][1]),
                             fminf(acc[mt][1][0], acc[mt][1][1]));
            float fb = fminf(fminf(acc[mt][0][2], acc[mt][0][3]),
                             fminf(acc[mt][1][2], acc[mt][1][3]));
            atomicMin(&rmin[r],     fkey(fa));
            atomicMin(&rmin[r + 8], fkey(fb));
        }
        __syncthreads();
#pragma unroll
        for (int mt = 0; mt < 4; mt++) {
            int r  = wm * 64 + mt * 16 + g;
            float ma = finv(rmin[r]) + THR;
            float mb = finv(rmin[r + 8]) + THR;
#pragma unroll
            for (int nt = 0; nt < 2; nt++) {
                int n = c * BN + wn * 16 + nt * 8 + 2 * t;
                if (acc[mt][nt][0] <= ma) {
                    int s = atomicAdd(&cnt[r], 1);
                    if (s < CAP) cand[r * CAP + s] = n;
                }
                if (acc[mt][nt][1] <= ma) {
                    int s = atomicAdd(&cnt[r], 1);
                    if (s < CAP) cand[r * CAP + s] = n + 1;
                }
                if (acc[mt][nt][2] <= mb) {
                    int s = atomicAdd(&cnt[r + 8], 1);
                    if (s < CAP) cand[(r + 8) * CAP + s] = n;
                }
                if (acc[mt][nt][3] <= mb) {
                    int s = atomicAdd(&cnt[r + 8], 1);
                    if (s < CAP) cand[(r + 8) * CAP + s] = n + 1;
                }
            }
        }
        // note: next iteration's prefetch into this buf is safe — every thread
        // passed the post-MMA __syncthreads above before any cp.async is issued.
    }
    __syncthreads();

    // ---- exact fp32 rescore (XLA-quantized formula, lexicographic min) ----
    for (int rr = 0; rr < 16; rr++) {
        int r = wid * 16 + rr;
        int m = m0 + r;
        const float4* zp = reinterpret_cast<const float4*>(z + (size_t)m * D) + lane * 2;
        float4 za = zp[0], zb = zp[1];
        float z2v = g_z2[m];
        int nct = cnt[r];
        float bestv = FLT_MAX; int besti = 0;
        int total = (nct > CAP) ? NE : nct;
        for (int j = 0; j < total; j++) {
            int n = (nct > CAP) ? j : cand[r * CAP + j];
            const float4* ep = reinterpret_cast<const float4*>(emb + (size_t)n * D) + lane * 2;
            float4 ea = ep[0], eb = ep[1];
            float d = za.x * ea.x + za.y * ea.y + za.z * ea.z + za.w * ea.w
                    + zb.x * eb.x + zb.y * eb.y + zb.z * eb.z + zb.w * eb.w;
#pragma unroll
            for (int o = 16; o; o >>= 1) d += __shfl_xor_sync(0xffffffffu, d, o);
            float v = z2v - 2.0f * d;          // fl(z2 - 2 dot)
            float s = v + g_e2[n];             // fl(... + e2): XLA lattice
            if (s < bestv || (s == bestv && n < besti)) { bestv = s; besti = n; }
        }
        if (lane == 0) { g_idx[m] = besti; out_idx[m] = (float)besti; }
    }
}

// ---------------- gather + STE + loss (unchanged, bit-stable) ----------------
__global__ void gather_loss(const float* __restrict__ z, const float* __restrict__ emb,
                            float* __restrict__ out_zq) {
    int tk = blockIdx.x, d = threadIdx.x;
    int e = g_idx[tk];
    float zq = emb[(size_t)e * D + d];
    float zz = z[(size_t)tk * D + d];
    float diff = zq - zz;
    out_zq[(size_t)tk * D + d] = zz + diff;    // fl(z + fl(z_q - z))
    float sq = diff * diff;
    __shared__ float red[8];
#pragma unroll
    for (int o = 16; o; o >>= 1) sq += __shfl_down_sync(0xffffffffu, sq, o);
    if ((d & 31) == 0) red[d >> 5] = sq;
    __syncthreads();
    if (d < 8) {
        float s = red[d];
#pragma unroll
        for (int o = 4; o; o >>= 1) s += __shfl_down_sync(0xffu, s, o);
        if (d == 0) g_partial[tk] = s;
    }
}

__global__ void finalize_loss(float* __restrict__ out_loss) {
    __shared__ double red[8];
    double s = 0.0;
    for (int i = threadIdx.x; i < TOK; i += 256) s += (double)g_partial[i];
#pragma unroll
    for (int o = 16; o; o >>= 1) s += __shfl_down_sync(0xffffffffu, s, o);
    if ((threadIdx.x & 31) == 0) red[threadIdx.x >> 5] = s;
    __syncthreads();
    if (threadIdx.x < 8) {
        double v = red[threadIdx.x];
#pragma unroll
        for (int o = 4; o; o >>= 1) v += __shfl_down_sync(0xffu, v, o);
        if (threadIdx.x == 0)
            out_loss[0] = (float)(1.25 * (v / (double)((size_t)TOK * D)));
    }
}

// ---------------------------------------------------------------------------
extern "C" void kernel_launch(void* const* d_in, const int* in_sizes, int n_in,
                              void* d_out, int out_size) {
    const float* z   = (const float*)d_in[0];
    const float* emb = (const float*)d_in[1];

    float* out      = (float*)d_out;
    float* out_zq   = out;
    float* out_loss = out + (size_t)TOK * D;
    float* out_idx  = out + (size_t)TOK * D + 1;

    cudaFuncSetAttribute(vq_main, cudaFuncAttributeMaxDynamicSharedMemorySize, SM_TOT);

    rowsq_emb<<<NE / 8, 256>>>(emb);
    rowsq_z<<<TOK / 8, 256>>>(z);
    conv_emb<<<2048, 256>>>(emb);
    vq_main<<<TOK / BM, 256, SM_TOT>>>(z, emb, out_idx);
    gather_loss<<<TOK, 256>>>(z, emb, out_zq);
    finalize_loss<<<1, 256>>>(out_loss);
}

// round 13
// speedup vs baseline: 18.5719x; 18.5719x over previous
#include <cuda_runtime.h>
#include <cuda_bf16.h>
#include <float.h>
#include <stdint.h>

#define D     256
#define NE    8192
#define TOK   32768
#define BM    128           // tokens per CTA
#define BN    128           // codes per chunk
#define NCH   (NE / BN)     // 64 chunks
#define CAP   32
#define WWIN  1.4e-4f       // 2*ulp(256) + 2x bf16 dot error margin (sigma=2.26e-3)

// ---------------- device scratch (no allocations allowed) -------------------
__device__ __align__(16) float g_e2[NE];
__device__ __align__(16) float g_z2[TOK];
__device__ int    g_idx[TOK];
__device__ float  g_partial[TOK];
__device__ uint4  g_ebh[NE * 32];      // emb as bf16, row-major [NE][256] (512B/row)

// ---------------- helpers ---------------------------------------------------
__device__ __forceinline__ uint32_t smem_u32(const void* p) {
    uint32_t a;
    asm("{ .reg .u64 t; cvta.to.shared.u64 t, %1; cvt.u32.u64 %0, t; }"
        : "=r"(a) : "l"(p));
    return a;
}
__device__ __forceinline__ void ldm4(uint32_t* r, uint32_t addr) {
    asm volatile("ldmatrix.sync.aligned.m8n8.x4.shared.b16 {%0,%1,%2,%3}, [%4];"
                 : "=r"(r[0]), "=r"(r[1]), "=r"(r[2]), "=r"(r[3]) : "r"(addr));
}
__device__ __forceinline__ void mma16816(float* c, const uint32_t* a, const uint32_t* b) {
    asm volatile(
        "mma.sync.aligned.m16n8k16.row.col.f32.bf16.bf16.f32 "
        "{%0,%1,%2,%3}, {%4,%5,%6,%7}, {%8,%9}, {%0,%1,%2,%3};"
        : "+f"(c[0]), "+f"(c[1]), "+f"(c[2]), "+f"(c[3])
        : "r"(a[0]), "r"(a[1]), "r"(a[2]), "r"(a[3]), "r"(b[0]), "r"(b[1]));
}
#define CP16(dst, src) asm volatile("cp.async.cg.shared.global [%0], [%1], 16;" :: "r"(dst), "l"(src))
#define CP_COMMIT()    asm volatile("cp.async.commit_group;" ::: "memory")
#define CP_WAIT(n)     asm volatile("cp.async.wait_group %0;" :: "n"(n) : "memory")

__device__ __forceinline__ uint32_t fkey(float x) {
    uint32_t u = __float_as_uint(x);
    return (u & 0x80000000u) ? ~u : (u | 0x80000000u);
}
__device__ __forceinline__ float finv(uint32_t k) {
    uint32_t u = (k & 0x80000000u) ? (k & 0x7FFFFFFFu) : ~k;
    return __uint_as_float(u);
}
__device__ __forceinline__ unsigned pk(__nv_bfloat16 a, __nv_bfloat16 b) {
    return ((unsigned)__bfloat16_as_ushort(b) << 16) | __bfloat16_as_ushort(a);
}

// ---------------- exact row sum-of-squares (bit-stable, round-1) ------------
__global__ void rowsq_emb(const float* __restrict__ emb) {
    int row = blockIdx.x * 8 + (threadIdx.x >> 5), lane = threadIdx.x & 31;
    const float4* e = reinterpret_cast<const float4*>(emb + (size_t)row * D);
    float s = 0.f;
#pragma unroll
    for (int c = 0; c < 2; c++) {
        float4 v = e[lane + 32 * c];
        s += v.x * v.x + v.y * v.y + v.z * v.z + v.w * v.w;
    }
#pragma unroll
    for (int o = 16; o; o >>= 1) s += __shfl_down_sync(0xffffffffu, s, o);
    if (lane == 0) g_e2[row] = s;
}
__global__ void rowsq_z(const float* __restrict__ z) {
    int row = blockIdx.x * 8 + (threadIdx.x >> 5), lane = threadIdx.x & 31;
    const float4* e = reinterpret_cast<const float4*>(z + (size_t)row * D);
    float s = 0.f;
#pragma unroll
    for (int c = 0; c < 2; c++) {
        float4 v = e[lane + 32 * c];
        s += v.x * v.x + v.y * v.y + v.z * v.z + v.w * v.w;
    }
#pragma unroll
    for (int o = 16; o; o >>= 1) s += __shfl_down_sync(0xffffffffu, s, o);
    if (lane == 0) g_z2[row] = s;
}

// ---------------- emb -> bf16 ----------------------------------------------
__global__ void conv_emb(const float* __restrict__ emb) {
    int u = blockIdx.x * 256 + threadIdx.x;          // 524288 float4s
    float4 v = reinterpret_cast<const float4*>(emb)[u];
    uint2 h;
    h.x = pk(__float2bfloat16(v.x), __float2bfloat16(v.y));
    h.y = pk(__float2bfloat16(v.z), __float2bfloat16(v.w));
    reinterpret_cast<uint2*>(g_ebh)[u] = h;
}

// ---------------- main: two-phase bf16 MMA filter + exact rescore -----------
// SMEM map (bytes):
#define SM_A    0                       // 128 x 512  = 65536  (z bf16, swizzled)
#define SM_B    65536                   // 2 x 128x512 = 131072 (emb chunk dbl-buf)
#define SM_E2   196608                  // 2 x 512
#define SM_RMIN 197632                  // 128 x 4
#define SM_CNT  198144                  // 128 x 4
#define SM_CAND 198656                  // 128 x CAP x 2 = 8192
#define SM_TOT  206848

__global__ void __launch_bounds__(512, 1)
vq_main(const float* __restrict__ z, const float* __restrict__ emb,
        float* __restrict__ out_idx) {
    extern __shared__ char sm[];
    const int tid  = threadIdx.x;
    const int lane = tid & 31;
    const int wid  = tid >> 5;          // 0..15
    const int wm   = wid >> 1;          // 0..7  : 16-row M slice
    const int wn   = wid & 1;           // 0..1  : 64-col N half
    const int g    = lane >> 2;
    const int t    = lane & 3;
    const int m0   = blockIdx.x * BM;
    const uint32_t smb = smem_u32(sm);

    float*     e2s  = reinterpret_cast<float*>(sm + SM_E2);
    unsigned*  rmin = reinterpret_cast<unsigned*>(sm + SM_RMIN);
    int*       cnt  = reinterpret_cast<int*>(sm + SM_CNT);
    unsigned short* cand = reinterpret_cast<unsigned short*>(sm + SM_CAND);

    if (tid < BM) { rmin[tid] = 0xFFFFFFFFu; cnt[tid] = 0; }

    // ---- convert CTA's 128 z rows to bf16 into A (XOR-swizzled 512B rows) ----
    for (int u = tid; u < BM * 64; u += 512) {       // 8192 float4s
        int r = u >> 6, c4 = u & 63;
        float4 v = reinterpret_cast<const float4*>(z + (size_t)(m0 + r) * D)[c4];
        uint2 h;
        h.x = pk(__float2bfloat16(v.x), __float2bfloat16(v.y));
        h.y = pk(__float2bfloat16(v.z), __float2bfloat16(v.w));
        uint32_t off = (uint32_t)r * 512 + ((((uint32_t)(c4 >> 1)) ^ (r & 7)) << 4)
                     + (c4 & 1) * 8;
        *reinterpret_cast<uint2*>(sm + SM_A + off) = h;
    }

    // ---- prefetch chunk 0 into buf 0 ----
    {
        const char* src = reinterpret_cast<const char*>(g_ebh);
        for (int u = tid; u < 4096; u += 512) {
            int r = u >> 5, c = u & 31;
            CP16(smb + SM_B + (uint32_t)r * 512 + (((uint32_t)(c ^ (r & 7))) << 4),
                 src + (size_t)r * 512 + c * 16);
        }
        if (tid < 32)
            CP16(smb + SM_E2 + tid * 16, reinterpret_cast<const char*>(g_e2) + tid * 16);
        CP_COMMIT();
    }

    // ---- fragment addressing (textbook m16n8k16, XOR swizzle s = lane&7) ----
    const uint32_t s    = lane & 7;
    const uint32_t aRow = (uint32_t)(wm * 16 + ((lane >> 3) & 1) * 8 + (lane & 7));
    const uint32_t aK8  = (uint32_t)(lane >> 4);
    const uint32_t aBase = smb + SM_A + aRow * 512;
    const uint32_t bK8  = (uint32_t)((lane >> 3) & 1);
    const uint32_t bRowOff = (uint32_t)((lane >> 4) * 8 + (lane & 7));
    uint32_t bBase[4];
#pragma unroll
    for (int p = 0; p < 4; p++)
        bBase[p] = smb + SM_B + (uint32_t)(wn * 64 + p * 16 + bRowOff) * 512;

    const int row0 = wm * 16 + g;
    const int row1 = row0 + 8;
    float locm0 = FLT_MAX, locm1 = FLT_MAX;
    float thr0 = 0.f, thr1 = 0.f;

    for (int cc = 0; cc < 2 * NCH; cc++) {
        const int ch  = cc & (NCH - 1);
        const int buf = cc & 1;

        if (cc + 1 < 2 * NCH) {                     // prefetch next chunk
            const int nc = (cc + 1) & (NCH - 1);
            const int nb = 1 - buf;
            const char* src = reinterpret_cast<const char*>(g_ebh) + (size_t)nc * BN * 512;
            for (int u = tid; u < 4096; u += 512) {
                int r = u >> 5, c = u & 31;
                CP16(smb + SM_B + (uint32_t)nb * 65536 + (uint32_t)r * 512
                         + (((uint32_t)(c ^ (r & 7))) << 4),
                     src + (size_t)r * 512 + c * 16);
            }
            if (tid < 32)
                CP16(smb + SM_E2 + (uint32_t)nb * 512 + tid * 16,
                     reinterpret_cast<const char*>(g_e2) + (size_t)nc * 512 + tid * 16);
            CP_COMMIT();
            CP_WAIT(1);
        } else {
            CP_WAIT(0);
        }
        __syncthreads();                            // current chunk visible to all

        float acc[8][4];
#pragma unroll
        for (int nt = 0; nt < 8; nt++)
#pragma unroll
            for (int q = 0; q < 4; q++) acc[nt][q] = 0.f;

        const uint32_t bufAdd = (uint32_t)buf * 65536;
#pragma unroll
        for (int kk = 0; kk < 16; kk++) {
            uint32_t a[4];
            ldm4(a, aBase + ((((uint32_t)(2 * kk) + aK8) ^ s) << 4));
#pragma unroll
            for (int p = 0; p < 4; p++) {
                uint32_t b[4];
                ldm4(b, bBase[p] + bufAdd + ((((uint32_t)(2 * kk) + bK8) ^ s) << 4));
                mma16816(acc[2 * p],     a, b);
                mma16816(acc[2 * p + 1], a, b + 2);
            }
        }

        // ---- epilogue: f = e2 - 2*dot ----
        if (cc < NCH) {                             // phase 0: register minima only
#pragma unroll
            for (int nt = 0; nt < 8; nt++) {
                int colb = wn * 64 + nt * 8 + 2 * t;
                float e2a = e2s[buf * 128 + colb];
                float e2b = e2s[buf * 128 + colb + 1];
                float f0 = fmaf(-2.f, acc[nt][0], e2a);
                float f1 = fmaf(-2.f, acc[nt][1], e2b);
                float f2 = fmaf(-2.f, acc[nt][2], e2a);
                float f3 = fmaf(-2.f, acc[nt][3], e2b);
                locm0 = fminf(locm0, fminf(f0, f1));
                locm1 = fminf(locm1, fminf(f2, f3));
            }
        } else {                                    // phase 1: fixed-threshold append
#pragma unroll
            for (int nt = 0; nt < 8; nt++) {
                int colb = wn * 64 + nt * 8 + 2 * t;
                float e2a = e2s[buf * 128 + colb];
                float e2b = e2s[buf * 128 + colb + 1];
                float f0 = fmaf(-2.f, acc[nt][0], e2a);
                float f1 = fmaf(-2.f, acc[nt][1], e2b);
                float f2 = fmaf(-2.f, acc[nt][2], e2a);
                float f3 = fmaf(-2.f, acc[nt][3], e2b);
                int n = ch * BN + colb;
                if (f0 <= thr0) { int q = atomicAdd(&cnt[row0], 1); if (q < CAP) cand[row0 * CAP + q] = (unsigned short)n; }
                if (f1 <= thr0) { int q = atomicAdd(&cnt[row0], 1); if (q < CAP) cand[row0 * CAP + q] = (unsigned short)(n + 1); }
                if (f2 <= thr1) { int q = atomicAdd(&cnt[row1], 1); if (q < CAP) cand[row1 * CAP + q] = (unsigned short)n; }
                if (f3 <= thr1) { int q = atomicAdd(&cnt[row1], 1); if (q < CAP) cand[row1 * CAP + q] = (unsigned short)(n + 1); }
            }
        }

        if (cc == NCH - 1) {                        // phase boundary: publish rmin
            atomicMin(&rmin[row0], fkey(locm0));
            atomicMin(&rmin[row1], fkey(locm1));
        }
        __syncthreads();                            // readers done before overwrite
        if (cc == NCH - 1) {
            thr0 = finv(rmin[row0]) + WWIN;
            thr1 = finv(rmin[row1]) + WWIN;
        }
    }

    // ---- exact fp32 rescore (XLA-quantized score, first-index tie-break) ----
    for (int rr = 0; rr < 8; rr++) {
        int r = wid * 8 + rr;
        int m = m0 + r;
        const float4* zp = reinterpret_cast<const float4*>(z + (size_t)m * D) + lane * 2;
        float4 za = zp[0], zb = zp[1];
        float z2v = g_z2[m];
        int nct = cnt[r];
        bool fb = (nct > CAP);
        int total = fb ? NE : nct;
        float bestv = FLT_MAX; int besti = 0;
        for (int j = 0; j < total; j++) {
            int n = fb ? j : (int)cand[r * CAP + j];
            const float4* ep = reinterpret_cast<const float4*>(emb + (size_t)n * D) + lane * 2;
            float4 ea = ep[0], eb = ep[1];
            float d = za.x * ea.x + za.y * ea.y + za.z * ea.z + za.w * ea.w
                    + zb.x * eb.x + zb.y * eb.y + zb.z * eb.z + zb.w * eb.w;
#pragma unroll
            for (int o = 16; o; o >>= 1) d += __shfl_xor_sync(0xffffffffu, d, o);
            float v = z2v - 2.0f * d;               // fl(z2 - 2 dot)
            float sc = v + g_e2[n];                 // fl(... + e2): XLA lattice
            if (sc < bestv || (sc == bestv && n < besti)) { bestv = sc; besti = n; }
        }
        if (lane == 0) { g_idx[m] = besti; out_idx[m] = (float)besti; }
    }
}

// ---------------- gather + STE + loss (bit-stable, round-1) ------------------
__global__ void gather_loss(const float* __restrict__ z, const float* __restrict__ emb,
                            float* __restrict__ out_zq) {
    int tk = blockIdx.x, d = threadIdx.x;
    int e = g_idx[tk];
    float zq = emb[(size_t)e * D + d];
    float zz = z[(size_t)tk * D + d];
    float diff = zq - zz;
    out_zq[(size_t)tk * D + d] = zz + diff;          // fl(z + fl(z_q - z))
    float sq = diff * diff;
    __shared__ float red[8];
#pragma unroll
    for (int o = 16; o; o >>= 1) sq += __shfl_down_sync(0xffffffffu, sq, o);
    if ((d & 31) == 0) red[d >> 5] = sq;
    __syncthreads();
    if (d < 8) {
        float s = red[d];
#pragma unroll
        for (int o = 4; o; o >>= 1) s += __shfl_down_sync(0xffu, s, o);
        if (d == 0) g_partial[tk] = s;
    }
}

__global__ void finalize_loss(float* __restrict__ out_loss) {
    __shared__ double red[8];
    double s = 0.0;
    for (int i = threadIdx.x; i < TOK; i += 256) s += (double)g_partial[i];
#pragma unroll
    for (int o = 16; o; o >>= 1) s += __shfl_down_sync(0xffffffffu, s, o);
    if ((threadIdx.x & 31) == 0) red[threadIdx.x >> 5] = s;
    __syncthreads();
    if (threadIdx.x < 8) {
        double v = red[threadIdx.x];
#pragma unroll
        for (int o = 4; o; o >>= 1) v += __shfl_down_sync(0xffu, v, o);
        if (threadIdx.x == 0)
            out_loss[0] = (float)(1.25 * (v / (double)((size_t)TOK * D)));
    }
}

// ---------------------------------------------------------------------------
extern "C" void kernel_launch(void* const* d_in, const int* in_sizes, int n_in,
                              void* d_out, int out_size) {
    const float* z   = (const float*)d_in[0];
    const float* emb = (const float*)d_in[1];

    float* out      = (float*)d_out;
    float* out_zq   = out;
    float* out_loss = out + (size_t)TOK * D;
    float* out_idx  = out + (size_t)TOK * D + 1;

    cudaFuncSetAttribute(vq_main, cudaFuncAttributeMaxDynamicSharedMemorySize, SM_TOT);

    rowsq_emb<<<NE / 8, 256>>>(emb);
    rowsq_z<<<TOK / 8, 256>>>(z);
    conv_emb<<<2048, 256>>>(emb);
    vq_main<<<TOK / BM, 512, SM_TOT>>>(z, emb, out_idx);
    gather_loss<<<TOK, 256>>>(z, emb, out_zq);
    finalize_loss<<<1, 256>>>(out_loss);
}